// round 1
// baseline (speedup 1.0000x reference)
#include <cuda_runtime.h>
#include <math.h>

#define T_SEQ   4096
#define C_DIM   1024
#define NHEADS  16
#define HDIM    64

// ---------------- scratch (static device globals; no allocation) -------------
__device__ float g_normed[T_SEQ * C_DIM];
__device__ float g_q[T_SEQ * C_DIM];
__device__ float g_k[T_SEQ * C_DIM];
__device__ float g_v[T_SEQ * C_DIM];
__device__ float g_att[T_SEQ * C_DIM];

// ---------------- RMSNorm ----------------------------------------------------
__global__ void rmsnorm_kernel(const float* __restrict__ x,
                               const float* __restrict__ w,
                               float* __restrict__ out)
{
    int row = blockIdx.x;
    const float4* xr = reinterpret_cast<const float4*>(x + (size_t)row * C_DIM);
    float ss = 0.f;
    for (int i = threadIdx.x; i < C_DIM / 4; i += blockDim.x) {
        float4 v = xr[i];
        ss += v.x * v.x + v.y * v.y + v.z * v.z + v.w * v.w;
    }
#pragma unroll
    for (int o = 16; o; o >>= 1) ss += __shfl_xor_sync(0xffffffffu, ss, o);

    __shared__ float red[8];
    __shared__ float s_inv;
    if ((threadIdx.x & 31) == 0) red[threadIdx.x >> 5] = ss;
    __syncthreads();
    if (threadIdx.x == 0) {
        float tot = 0.f;
        int nw = blockDim.x >> 5;
        for (int i = 0; i < nw; i++) tot += red[i];
        s_inv = rsqrtf(tot * (1.0f / C_DIM) + 1e-6f);
    }
    __syncthreads();
    float inv = s_inv;
    const float4* wr = reinterpret_cast<const float4*>(w);
    float4* outr = reinterpret_cast<float4*>(out + (size_t)row * C_DIM);
    for (int i = threadIdx.x; i < C_DIM / 4; i += blockDim.x) {
        float4 v = xr[i], ww = wr[i];
        v.x = v.x * inv * ww.x;
        v.y = v.y * inv * ww.y;
        v.z = v.z * inv * ww.z;
        v.w = v.w * inv * ww.w;
        outr[i] = v;
    }
}

// ---------------- SGEMM: C[M,N] = A[M,K] * B[N,K]^T (+Res) -------------------
#define BM 128
#define BN 128
#define BK 8

__global__ __launch_bounds__(256, 2)
void sgemm_nt_kernel(const float* __restrict__ A, const float* __restrict__ B,
                     const float* __restrict__ Res, float* __restrict__ Cm,
                     int M, int N, int K)
{
    __shared__ float As[BK][BM];
    __shared__ float Bs[BK][BN];

    int tid = threadIdx.x;
    int lr = tid >> 1;
    int lc = (tid & 1) * 4;
    const float* Ag = A + (size_t)(blockIdx.y * BM + lr) * K + lc;
    const float* Bg = B + (size_t)(blockIdx.x * BN + lr) * K + lc;
    int tx = tid & 15, ty = tid >> 4;

    float acc[8][8];
#pragma unroll
    for (int i = 0; i < 8; i++)
#pragma unroll
        for (int j = 0; j < 8; j++) acc[i][j] = 0.f;

    for (int k0 = 0; k0 < K; k0 += BK) {
        float4 a = *reinterpret_cast<const float4*>(Ag + k0);
        float4 b = *reinterpret_cast<const float4*>(Bg + k0);
        As[lc + 0][lr] = a.x; As[lc + 1][lr] = a.y;
        As[lc + 2][lr] = a.z; As[lc + 3][lr] = a.w;
        Bs[lc + 0][lr] = b.x; Bs[lc + 1][lr] = b.y;
        Bs[lc + 2][lr] = b.z; Bs[lc + 3][lr] = b.w;
        __syncthreads();
#pragma unroll
        for (int k = 0; k < BK; k++) {
            float4 a0 = *reinterpret_cast<const float4*>(&As[k][ty * 8]);
            float4 a1 = *reinterpret_cast<const float4*>(&As[k][ty * 8 + 4]);
            float4 b0 = *reinterpret_cast<const float4*>(&Bs[k][tx * 8]);
            float4 b1 = *reinterpret_cast<const float4*>(&Bs[k][tx * 8 + 4]);
            float ar[8] = {a0.x, a0.y, a0.z, a0.w, a1.x, a1.y, a1.z, a1.w};
            float br[8] = {b0.x, b0.y, b0.z, b0.w, b1.x, b1.y, b1.z, b1.w};
#pragma unroll
            for (int i = 0; i < 8; i++)
#pragma unroll
                for (int j = 0; j < 8; j++)
                    acc[i][j] += ar[i] * br[j];
        }
        __syncthreads();
    }

#pragma unroll
    for (int i = 0; i < 8; i++) {
        int row = blockIdx.y * BM + ty * 8 + i;
        float* crow = Cm + (size_t)row * N + blockIdx.x * BN + tx * 8;
        if (Res) {
            const float* rrow = Res + (size_t)row * N + blockIdx.x * BN + tx * 8;
#pragma unroll
            for (int j = 0; j < 8; j++) acc[i][j] += rrow[j];
        }
        *reinterpret_cast<float4*>(crow) =
            make_float4(acc[i][0], acc[i][1], acc[i][2], acc[i][3]);
        *reinterpret_cast<float4*>(crow + 4) =
            make_float4(acc[i][4], acc[i][5], acc[i][6], acc[i][7]);
    }
}

// ---------------- RoPE (applied to q and k in place) -------------------------
__global__ void rope_kernel(float* __restrict__ q, float* __restrict__ k)
{
    int idx = blockIdx.x * blockDim.x + threadIdx.x;
    if (idx >= T_SEQ * NHEADS * 32) return;
    int i = idx & 31;
    int h = (idx >> 5) & (NHEADS - 1);
    int t = idx >> 9;
    float freq = powf(10000.0f, -(float)(2 * i) * (1.0f / 64.0f));
    float f = (float)t * freq;
    float s, c;
    sincosf(f, &s, &c);
    int base = t * C_DIM + h * HDIM;
    float q1 = q[base + i], q2 = q[base + i + 32];
    q[base + i]      = q1 * c - q2 * s;
    q[base + i + 32] = q2 * c + q1 * s;
    float k1 = k[base + i], k2 = k[base + i + 32];
    k[base + i]      = k1 * c - k2 * s;
    k[base + i + 32] = k2 * c + k1 * s;
}

// ---------------- Flash attention (causal, fp32, online softmax) -------------
#define FS 68   // smem row stride (floats): 16B-aligned rows, conflict-spread
#define FLASH_SMEM (4 * 64 * FS * 4)

__global__ __launch_bounds__(256)
void flash_kernel(const float* __restrict__ Qg, const float* __restrict__ Kg,
                  const float* __restrict__ Vg, float* __restrict__ Og)
{
    extern __shared__ float sm[];
    float* Qs = sm;              // [64][FS]  Qs[r][d]
    float* Ks = Qs + 64 * FS;    // [64][FS]  transposed: Ks[d][n]
    float* Vs = Ks + 64 * FS;    // [64][FS]  Vs[c][d]
    float* Ps = Vs + 64 * FS;    // [64][FS]  Ps[r][c]

    int qt = (gridDim.x - 1) - blockIdx.x;  // heavy tiles first
    int h  = blockIdx.y;
    int tid = threadIdx.x;
    int tx = tid & 15, ty = tid >> 4;
    int r0 = ty * 4, c0 = tx * 4;

    int lrow = tid >> 2;        // 0..63
    int lq   = tid & 3;         // quarter of a 64-float row

    // load Q tile [64 rows x 64 dh]
    {
        const float* src = Qg + (size_t)(qt * 64 + lrow) * C_DIM + h * HDIM + lq * 16;
        float* dst = Qs + lrow * FS + lq * 16;
#pragma unroll
        for (int v = 0; v < 4; v++)
            *reinterpret_cast<float4*>(dst + v * 4) =
                *reinterpret_cast<const float4*>(src + v * 4);
    }

    float o[4][4];
    float m[4], l[4];
#pragma unroll
    for (int i = 0; i < 4; i++) {
        m[i] = -INFINITY; l[i] = 0.f;
#pragma unroll
        for (int j = 0; j < 4; j++) o[i][j] = 0.f;
    }

    for (int j = 0; j <= qt; j++) {
        __syncthreads();  // prior tile's reads of Ks/Vs/Ps complete (also Q vis. on iter 0)
        // load K transposed + V
        {
            const float* ksrc = Kg + (size_t)(j * 64 + lrow) * C_DIM + h * HDIM + lq * 16;
#pragma unroll
            for (int v = 0; v < 4; v++) {
                float4 kv = *reinterpret_cast<const float4*>(ksrc + v * 4);
                int cb = lq * 16 + v * 4;
                Ks[(cb + 0) * FS + lrow] = kv.x;
                Ks[(cb + 1) * FS + lrow] = kv.y;
                Ks[(cb + 2) * FS + lrow] = kv.z;
                Ks[(cb + 3) * FS + lrow] = kv.w;
            }
            const float* vsrc = Vg + (size_t)(j * 64 + lrow) * C_DIM + h * HDIM + lq * 16;
            float* vdst = Vs + lrow * FS + lq * 16;
#pragma unroll
            for (int v = 0; v < 4; v++)
                *reinterpret_cast<float4*>(vdst + v * 4) =
                    *reinterpret_cast<const float4*>(vsrc + v * 4);
        }
        __syncthreads();

        // S = Q K^T  (4x4 microtile)
        float s[4][4];
#pragma unroll
        for (int i = 0; i < 4; i++)
#pragma unroll
            for (int jj = 0; jj < 4; jj++) s[i][jj] = 0.f;

        for (int k = 0; k < 64; k++) {
            float4 b = *reinterpret_cast<const float4*>(&Ks[k * FS + c0]);
#pragma unroll
            for (int i = 0; i < 4; i++) {
                float a = Qs[(r0 + i) * FS + k];
                s[i][0] += a * b.x; s[i][1] += a * b.y;
                s[i][2] += a * b.z; s[i][3] += a * b.w;
            }
        }

        // scale + causal mask (diagonal tile only)
        const float sc = 0.125f;  // 1/sqrt(64)
        if (j == qt) {
#pragma unroll
            for (int i = 0; i < 4; i++)
#pragma unroll
                for (int jj = 0; jj < 4; jj++) {
                    int rr = r0 + i, cc = c0 + jj;
                    s[i][jj] = (cc <= rr) ? s[i][jj] * sc : -INFINITY;
                }
        } else {
#pragma unroll
            for (int i = 0; i < 4; i++)
#pragma unroll
                for (int jj = 0; jj < 4; jj++) s[i][jj] *= sc;
        }

        // online softmax
        float alpha[4];
#pragma unroll
        for (int i = 0; i < 4; i++) {
            float rm = fmaxf(fmaxf(s[i][0], s[i][1]), fmaxf(s[i][2], s[i][3]));
#pragma unroll
            for (int off = 1; off < 16; off <<= 1)
                rm = fmaxf(rm, __shfl_xor_sync(0xffffffffu, rm, off, 16));
            float mnew = fmaxf(m[i], rm);
            alpha[i] = __expf(m[i] - mnew);
            m[i] = mnew;
            float rs = 0.f;
#pragma unroll
            for (int jj = 0; jj < 4; jj++) {
                float p = __expf(s[i][jj] - mnew);
                s[i][jj] = p;
                rs += p;
            }
#pragma unroll
            for (int off = 1; off < 16; off <<= 1)
                rs += __shfl_xor_sync(0xffffffffu, rs, off, 16);
            l[i] = l[i] * alpha[i] + rs;
            *reinterpret_cast<float4*>(&Ps[(r0 + i) * FS + c0]) =
                make_float4(s[i][0], s[i][1], s[i][2], s[i][3]);
        }
        __syncthreads();  // Ps visible to all

        // O = O*alpha + P V
#pragma unroll
        for (int i = 0; i < 4; i++)
#pragma unroll
            for (int jj = 0; jj < 4; jj++) o[i][jj] *= alpha[i];

        for (int c = 0; c < 64; c++) {
            float4 v4 = *reinterpret_cast<const float4*>(&Vs[c * FS + c0]);
#pragma unroll
            for (int i = 0; i < 4; i++) {
                float p = Ps[(r0 + i) * FS + c];
                o[i][0] += p * v4.x; o[i][1] += p * v4.y;
                o[i][2] += p * v4.z; o[i][3] += p * v4.w;
            }
        }
    }

    // epilogue: normalize + store
#pragma unroll
    for (int i = 0; i < 4; i++) {
        float invl = 1.f / l[i];
        float* dst = Og + (size_t)(qt * 64 + r0 + i) * C_DIM + h * HDIM + c0;
        *reinterpret_cast<float4*>(dst) =
            make_float4(o[i][0] * invl, o[i][1] * invl, o[i][2] * invl, o[i][3] * invl);
    }
}

// ---------------- launch -----------------------------------------------------
extern "C" void kernel_launch(void* const* d_in, const int* in_sizes, int n_in,
                              void* d_out, int out_size)
{
    const float* x      = (const float*)d_in[0];
    const float* wq     = (const float*)d_in[1];
    const float* wk     = (const float*)d_in[2];
    const float* wv     = (const float*)d_in[3];
    const float* wo     = (const float*)d_in[4];
    const float* norm_w = (const float*)d_in[5];
    float* out = (float*)d_out;

    float *normed, *q, *k, *v, *att;
    cudaGetSymbolAddress((void**)&normed, g_normed);
    cudaGetSymbolAddress((void**)&q,      g_q);
    cudaGetSymbolAddress((void**)&k,      g_k);
    cudaGetSymbolAddress((void**)&v,      g_v);
    cudaGetSymbolAddress((void**)&att,    g_att);

    // 1) RMSNorm
    rmsnorm_kernel<<<T_SEQ, 256>>>(x, norm_w, normed);

    // 2) Q/K/V projections: [4096,1024] @ W^T
    dim3 gdim(C_DIM / BN, T_SEQ / BM);
    sgemm_nt_kernel<<<gdim, 256>>>(normed, wq, nullptr, q, T_SEQ, C_DIM, C_DIM);
    sgemm_nt_kernel<<<gdim, 256>>>(normed, wk, nullptr, k, T_SEQ, C_DIM, C_DIM);
    sgemm_nt_kernel<<<gdim, 256>>>(normed, wv, nullptr, v, T_SEQ, C_DIM, C_DIM);

    // 3) RoPE on q,k
    int nrope = T_SEQ * NHEADS * 32;
    rope_kernel<<<(nrope + 255) / 256, 256>>>(q, k);

    // 4) causal flash attention
    cudaFuncSetAttribute(flash_kernel, cudaFuncAttributeMaxDynamicSharedMemorySize,
                         FLASH_SMEM);
    dim3 fgrid(T_SEQ / 64, NHEADS);
    flash_kernel<<<fgrid, 256, FLASH_SMEM>>>(q, k, v, att);

    // 5) output projection + residual
    sgemm_nt_kernel<<<gdim, 256>>>(att, wo, x, out, T_SEQ, C_DIM, C_DIM);
}